// round 13
// baseline (speedup 1.0000x reference)
#include <cuda_runtime.h>
#include <cstdint>

typedef unsigned long long ull;

static constexpr int BATCH  = 16;
static constexpr int NPTS   = 2048;
static constexpr int TOTAL  = BATCH * NPTS;    // 32768
static constexpr int KNN    = 6;
static constexpr int NSPLIT = 4;
static constexpr int CHUNK  = NPTS / NSPLIT;   // 512

// ---------------- scratch (device globals; no cudaMalloc allowed) ----------
__device__ float g_x0[TOTAL * 64];
__device__ float g_x1[TOTAL * 32];
__device__ float g_sq[TOTAL];
__device__ float g_pd[TOTAL * NSPLIT * KNN];
__device__ int   g_pi[TOTAL * NSPLIT * KNN];
// packed weights (feature-pair layout), shared SM-wide via L1 instead of
// being duplicated into every block's smem
__device__ ull   g_w1p0[32 * 64];
__device__ ull   g_w2p0[32 * 64];
__device__ ull   g_w1p1[64 * 32];
__device__ ull   g_w2p1[16 * 32];
__device__ ull   g_w1p2[32 * 64];
__device__ ull   g_w2p2[32 * 64];

// ---------------- f32x2 helpers --------------------------------------------
__device__ __forceinline__ ull fma2(ull a, ull b, ull c) {
    ull d;
    asm("fma.rn.f32x2 %0, %1, %2, %3;" : "=l"(d) : "l"(a), "l"(b), "l"(c));
    return d;
}
__device__ __forceinline__ ull pack2(float x, float y) {
    ull r;
    asm("mov.b64 %0, {%1, %2};" : "=l"(r) : "f"(x), "f"(y));
    return r;
}
__device__ __forceinline__ void unpack2(ull v, float& x, float& y) {
    asm("mov.b64 {%0, %1}, %2;" : "=f"(x), "=f"(y) : "l"(v));
}

// ---------------- squared norms (input layer only) -------------------------
template <int C>
__global__ void sq_kernel(const float* __restrict__ x, float* __restrict__ sq) {
    int p = blockIdx.x * 256 + threadIdx.x;
    if (p >= TOTAL) return;
    const float4* xp = reinterpret_cast<const float4*>(x + (size_t)p * C);
    float s = 0.f;
#pragma unroll
    for (int i = 0; i < C / 4; i++) {
        float4 v = xp[i];
        s += v.x * v.x + v.y * v.y + v.z * v.z + v.w * v.w;
    }
    sq[p] = s;
}

// ---------------- weight prepack (paired rows), all 3 layers in one launch --
// w1p[q*H + c]    = {W1[2q][c],   W1[2q+1][c]}   for q in [0, CIN)
// w2p[q*COUT + c] = {W2[2q][c],   W2[2q+1][c]}   for q in [0, H/2)
__device__ void prepack_one(const float* W1, const float* W2,
                            ull* w1p, ull* w2p, int CIN, int H, int COUT,
                            int idx) {
    if (idx < CIN * H) {
        int q = idx / H, c = idx % H;
        w1p[idx] = pack2(W1[(2 * q) * H + c], W1[(2 * q + 1) * H + c]);
    }
    if (idx < (H / 2) * COUT) {
        int q = idx / COUT, c = idx % COUT;
        w2p[idx] = pack2(W2[(2 * q) * COUT + c], W2[(2 * q + 1) * COUT + c]);
    }
}
__global__ void prepack_all_kernel(const float* W1_0, const float* W2_0,
                                   const float* W1_1, const float* W2_1,
                                   const float* W1_2, const float* W2_2,
                                   ull* w1p0, ull* w2p0,
                                   ull* w1p1, ull* w2p1,
                                   ull* w1p2, ull* w2p2) {
    int idx = blockIdx.x * 256 + threadIdx.x;
    if (blockIdx.y == 0)      prepack_one(W1_0, W2_0, w1p0, w2p0, 32, 64, 64, idx);
    else if (blockIdx.y == 1) prepack_one(W1_1, W2_1, w1p1, w2p1, 64, 32, 32, idx);
    else                      prepack_one(W1_2, W2_2, w1p2, w2p2, 32, 64, 64, idx);
}

// ---------------- partial kNN over one candidate chunk ---------------------
// block: 128 queries of one batch; MT-candidate tiles staged in smem in
// feature-paired layout, monolithic MT-wide accumulator burst (max ILP).
// MT=16 for C=32, MT=8 for C=64. Rank by csq - 2*dot (query norm cancels).
template <int C, int MT>
__global__ void __launch_bounds__(128)
knn_part_kernel(const float* __restrict__ x,
                const float* __restrict__ sq,
                float* __restrict__ pd, int* __restrict__ pi) {
    constexpr int SP = MT * 2 + 4;     // float stride per feature-pair row
    static_assert(MT * C == 128 * 4, "one float4 per thread per tile");
    __shared__ __align__(16) float scs[(C / 2) * SP];
    __shared__ float ssq[MT];

    const int b     = blockIdx.y;
    const int chunk = blockIdx.z;
    const int tid   = threadIdx.x;
    const int q     = blockIdx.x * 128 + tid;
    const float* xb = x + (size_t)b * NPTS * C;
    const float* sb = sq + b * NPTS;

    // query features into packed-pair registers
    ull qf[C / 2];
#pragma unroll
    for (int ip = 0; ip < C / 4; ip++) {
        float4 v = *reinterpret_cast<const float4*>(xb + (size_t)q * C + ip * 4);
        qf[2 * ip]     = pack2(v.x, v.y);
        qf[2 * ip + 1] = pack2(v.z, v.w);
    }

    const float INF = __int_as_float(0x7f800000);
    float kd[6] = {INF, INF, INF, INF, INF, INF};
    int   ki[6] = {0, 0, 0, 0, 0, 0};

    const int m_beg = chunk * CHUNK;
    for (int m0 = m_beg; m0 < m_beg + CHUNK; m0 += MT) {
        __syncthreads();
        {
            int f  = tid * 4;
            int mm = f / C, i = f % C;
            float4 v = *reinterpret_cast<const float4*>(
                xb + (size_t)(m0 + mm) * C + i);
            *reinterpret_cast<float2*>(&scs[(i >> 1) * SP + mm * 2])       = make_float2(v.x, v.y);
            *reinterpret_cast<float2*>(&scs[((i >> 1) + 1) * SP + mm * 2]) = make_float2(v.z, v.w);
        }
        if (tid < MT) ssq[tid] = sb[m0 + tid];
        __syncthreads();

        ull acc[MT];
#pragma unroll
        for (int mm = 0; mm < MT; mm++) acc[mm] = 0ull;

#pragma unroll
        for (int ip = 0; ip < C / 2; ip++) {
            ull qv = qf[ip];
            const ulonglong2* base =
                reinterpret_cast<const ulonglong2*>(&scs[ip * SP]);
#pragma unroll
            for (int mm2 = 0; mm2 < MT / 2; mm2++) {
                ulonglong2 cc = base[mm2];
                acc[2 * mm2]     = fma2(qv, cc.x, acc[2 * mm2]);
                acc[2 * mm2 + 1] = fma2(qv, cc.y, acc[2 * mm2 + 1]);
            }
        }

#pragma unroll
        for (int mm = 0; mm < MT; mm++) {
            float lo, hi;
            unpack2(acc[mm], lo, hi);
            float d = fmaf(-2.f, lo + hi, ssq[mm]);   // csq - 2*dot
            int   m = m0 + mm;
            if (m != q && d < kd[5]) {   // strict < keeps lower index on ties
                kd[5] = d; ki[5] = m;
#pragma unroll
                for (int j = 5; j > 0; j--) {
                    if (kd[j] < kd[j - 1]) {
                        float td = kd[j]; kd[j] = kd[j - 1]; kd[j - 1] = td;
                        int   ti = ki[j]; ki[j] = ki[j - 1]; ki[j - 1] = ti;
                    }
                }
            }
        }
    }

    const int base = ((b * NPTS + q) * NSPLIT + chunk) * KNN;
#pragma unroll
    for (int k = 0; k < KNN; k++) {
        pd[base + k] = kd[k];
        pi[base + k] = b * NPTS + ki[k];
    }
}

// ---------------- edge MLP + max over K + (residual) + relu ----------------
// warp per point-group (8 points, processed in pairs so each weight fetch
// feeds 2 points x 6 edges x CH fma2). Weights come from prepacked GLOBAL
// arrays via __ldg (L1-resident, shared SM-wide). The NSPLIT partial top-6
// lists are merged INLINE in the warp prologue (lanes 0..7, one point each;
// entries consumed in chunk order with strict-< insertion — identical
// selection semantics to the old standalone merge kernel), eliminating the
// merge launches and the global knn round-trip entirely.
// xi half of stage-1 computed once per point.
// WSQ: fused output-row-norm write (feeds the next layer's kNN).
template <int CIN, int H, int COUT, bool RES, bool WSQ>
__global__ void __launch_bounds__(64)
edge_kernel(const float* __restrict__ x,
            const float* __restrict__ pd, const int* __restrict__ pi,
            const ull* __restrict__ w1p, const float* __restrict__ b1,
            const ull* __restrict__ w2p, const float* __restrict__ b2,
            const float* __restrict__ res, float* __restrict__ out,
            float* __restrict__ osq) {
    constexpr int WPB = 2;            // warps per block
    constexpr int PPW = 8;            // points per warp
    constexpr int PB  = 2;            // points processed together
    constexpr int CH  = H / 32;       // h1 channels per lane
    constexpr int CO  = COUT / 32;    // out channels per lane
    constexpr int RIN = CIN / 32;     // input features per lane

    __shared__ __align__(16) ull xiu[WPB][PB][CIN / 2];
    __shared__ __align__(16) ull dgu[WPB][PB][KNN][CIN / 2];
    __shared__ __align__(16) ull hbu[WPB][PB][KNN][H / 2];
    __shared__ int knn_s[WPB][PPW][KNN];

    const int tid  = threadIdx.x;
    const int w    = tid >> 5;
    const int lane = tid & 31;

    float b1v[CH], b2v[CO];
#pragma unroll
    for (int cc = 0; cc < CH; cc++) b1v[cc] = b1[lane + 32 * cc];
#pragma unroll
    for (int cc = 0; cc < CO; cc++) b2v[cc] = b2[lane + 32 * cc];

    const float NINF = __int_as_float(0xff800000);
    const int p0 = (blockIdx.x * WPB + w) * PPW;

    // ---- inline merge of NSPLIT partial lists: lane l merges point p0+l ----
    if (lane < PPW) {
        const float INF = __int_as_float(0x7f800000);
        float kd[6] = {INF, INF, INF, INF, INF, INF};
        int   ki[6] = {0, 0, 0, 0, 0, 0};
        const int base = (p0 + lane) * NSPLIT * KNN;
#pragma unroll
        for (int e = 0; e < NSPLIT * KNN; e++) {
            float d = pd[base + e];
            int   i = pi[base + e];
            if (d < kd[5]) {
                kd[5] = d; ki[5] = i;
#pragma unroll
                for (int j = 5; j > 0; j--) {
                    if (kd[j] < kd[j - 1]) {
                        float td = kd[j]; kd[j] = kd[j - 1]; kd[j - 1] = td;
                        int   ti = ki[j]; ki[j] = ki[j - 1]; ki[j - 1] = ti;
                    }
                }
            }
        }
#pragma unroll
        for (int k = 0; k < KNN; k++) knn_s[w][lane][k] = ki[k];
    }
    __syncwarp();

    for (int pt = 0; pt < PPW; pt += PB) {
        // xi + neighbor diffs into per-warp smem for both points
        float xr[PB][RIN];
#pragma unroll
        for (int pp = 0; pp < PB; pp++) {
            const int P = p0 + pt + pp;
            float* xif = reinterpret_cast<float*>(xiu[w][pp]);
#pragma unroll
            for (int r = 0; r < RIN; r++) {
                xr[pp][r] = x[(size_t)P * CIN + lane + 32 * r];
                xif[lane + 32 * r] = xr[pp][r];
            }
#pragma unroll
            for (int k = 0; k < KNN; k++) {
                int j = knn_s[w][pt + pp][k];
                float* dgf = reinterpret_cast<float*>(dgu[w][pp][k]);
#pragma unroll
                for (int r = 0; r < RIN; r++)
                    dgf[lane + 32 * r] =
                        x[(size_t)j * CIN + lane + 32 * r] - xr[pp][r];
            }
        }
        __syncwarp();

        // stage 1 base: xi @ W1[:CIN] (edge-invariant, shared weight loads)
        ull ab[PB][CH];
#pragma unroll
        for (int pp = 0; pp < PB; pp++)
#pragma unroll
            for (int cc = 0; cc < CH; cc++) ab[pp][cc] = 0ull;
#pragma unroll
        for (int ip = 0; ip < CIN / 2; ip++) {
            ull wv[CH];
#pragma unroll
            for (int cc = 0; cc < CH; cc++)
                wv[cc] = __ldg(&w1p[ip * H + lane + 32 * cc]);
#pragma unroll
            for (int pp = 0; pp < PB; pp++) {
                ull xv = xiu[w][pp][ip];
#pragma unroll
                for (int cc = 0; cc < CH; cc++)
                    ab[pp][cc] = fma2(xv, wv[cc], ab[pp][cc]);
            }
        }

        // stage 1 per edge: + (xj-xi) @ W1[CIN:]
        ull a2[PB][KNN][CH];
#pragma unroll
        for (int pp = 0; pp < PB; pp++)
#pragma unroll
            for (int k = 0; k < KNN; k++)
#pragma unroll
                for (int cc = 0; cc < CH; cc++) a2[pp][k][cc] = ab[pp][cc];
#pragma unroll
        for (int ip = 0; ip < CIN / 2; ip++) {
            ull wv[CH];
#pragma unroll
            for (int cc = 0; cc < CH; cc++)
                wv[cc] = __ldg(&w1p[(CIN / 2 + ip) * H + lane + 32 * cc]);
#pragma unroll
            for (int pp = 0; pp < PB; pp++)
#pragma unroll
                for (int k = 0; k < KNN; k++) {
                    ull dv = dgu[w][pp][k][ip];
#pragma unroll
                    for (int cc = 0; cc < CH; cc++)
                        a2[pp][k][cc] = fma2(dv, wv[cc], a2[pp][k][cc]);
                }
        }
#pragma unroll
        for (int pp = 0; pp < PB; pp++)
#pragma unroll
            for (int k = 0; k < KNN; k++) {
                float* hbf = reinterpret_cast<float*>(hbu[w][pp][k]);
#pragma unroll
                for (int cc = 0; cc < CH; cc++) {
                    float lo, hi;
                    unpack2(a2[pp][k][cc], lo, hi);
                    hbf[lane + 32 * cc] = fmaxf(b1v[cc] + lo + hi, 0.f);
                }
            }
        __syncwarp();

        // stage 2: o = h1 @ W2 + b2, max over edges
        ull o2[PB][KNN][CO];
#pragma unroll
        for (int pp = 0; pp < PB; pp++)
#pragma unroll
            for (int k = 0; k < KNN; k++)
#pragma unroll
                for (int cc = 0; cc < CO; cc++) o2[pp][k][cc] = 0ull;
#pragma unroll
        for (int hp = 0; hp < H / 2; hp++) {
            ull wv[CO];
#pragma unroll
            for (int cc = 0; cc < CO; cc++)
                wv[cc] = __ldg(&w2p[hp * COUT + lane + 32 * cc]);
#pragma unroll
            for (int pp = 0; pp < PB; pp++)
#pragma unroll
                for (int k = 0; k < KNN; k++) {
                    ull hv = hbu[w][pp][k][hp];
#pragma unroll
                    for (int cc = 0; cc < CO; cc++)
                        o2[pp][k][cc] = fma2(hv, wv[cc], o2[pp][k][cc]);
                }
        }
#pragma unroll
        for (int pp = 0; pp < PB; pp++) {
            const int P = p0 + pt + pp;
            float best[CO];
#pragma unroll
            for (int cc = 0; cc < CO; cc++) best[cc] = NINF;
#pragma unroll
            for (int k = 0; k < KNN; k++)
#pragma unroll
                for (int cc = 0; cc < CO; cc++) {
                    float lo, hi;
                    unpack2(o2[pp][k][cc], lo, hi);
                    best[cc] = fmaxf(best[cc], b2v[cc] + lo + hi);
                }
            float sq_acc = 0.f;
#pragma unroll
            for (int cc = 0; cc < CO; cc++) {
                int c = lane + 32 * cc;
                float v = best[cc];
                if (RES) v += res[(size_t)P * COUT + c];
                v = fmaxf(v, 0.f);
                out[(size_t)P * COUT + c] = v;
                if (WSQ) sq_acc = fmaf(v, v, sq_acc);
            }
            if (WSQ) {
                // warp-wide sum of per-lane channel squares
#pragma unroll
                for (int off = 16; off > 0; off >>= 1)
                    sq_acc += __shfl_xor_sync(0xffffffffu, sq_acc, off);
                if (lane == 0) osq[P] = sq_acc;
            }
        }
        __syncwarp();
    }
}

// ---------------- launch ----------------------------------------------------
extern "C" void kernel_launch(void* const* d_in, const int* in_sizes, int n_in,
                              void* d_out, int out_size) {
    const float* x    = (const float*)d_in[0];
    const float* W1_0 = (const float*)d_in[2];
    const float* b1_0 = (const float*)d_in[3];
    const float* W2_0 = (const float*)d_in[4];
    const float* b2_0 = (const float*)d_in[5];
    const float* W1_1 = (const float*)d_in[6];
    const float* b1_1 = (const float*)d_in[7];
    const float* W2_1 = (const float*)d_in[8];
    const float* b2_1 = (const float*)d_in[9];
    const float* W1_2 = (const float*)d_in[10];
    const float* b1_2 = (const float*)d_in[11];
    const float* W2_2 = (const float*)d_in[12];
    const float* b2_2 = (const float*)d_in[13];
    float* out = (float*)d_out;

    float *px0, *px1, *psq, *ppd;
    int *ppi;
    ull *pw1p0, *pw2p0, *pw1p1, *pw2p1, *pw1p2, *pw2p2;
    cudaGetSymbolAddress((void**)&px0, g_x0);
    cudaGetSymbolAddress((void**)&px1, g_x1);
    cudaGetSymbolAddress((void**)&psq, g_sq);
    cudaGetSymbolAddress((void**)&ppd, g_pd);
    cudaGetSymbolAddress((void**)&ppi, g_pi);
    cudaGetSymbolAddress((void**)&pw1p0, g_w1p0);
    cudaGetSymbolAddress((void**)&pw2p0, g_w2p0);
    cudaGetSymbolAddress((void**)&pw1p1, g_w1p1);
    cudaGetSymbolAddress((void**)&pw2p1, g_w2p1);
    cudaGetSymbolAddress((void**)&pw1p2, g_w1p2);
    cudaGetSymbolAddress((void**)&pw2p2, g_w2p2);

    dim3 knn_grid(NPTS / 128, BATCH, NSPLIT);
    const int edge_grid = TOTAL / (2 * 8);   // WPB*PPW points per block

    // weight prepack for all layers (one launch) + input row norms
    prepack_all_kernel<<<dim3(8, 3), 256>>>(W1_0, W2_0, W1_1, W2_1, W1_2, W2_2,
                                            pw1p0, pw2p0, pw1p1, pw2p1,
                                            pw1p2, pw2p2);
    sq_kernel<32><<<TOTAL / 256, 256>>>(x, psq);

    // ---- layer 0: x(32) -> x0(64), relu (+ row norms for next kNN)
    knn_part_kernel<32, 16><<<knn_grid, 128>>>(x, psq, ppd, ppi);
    edge_kernel<32, 64, 64, false, true><<<edge_grid, 64>>>(
        x, ppd, ppi, pw1p0, b1_0, pw2p0, b2_0, nullptr, px0, psq);

    // ---- layer 1: x0(64) -> x1(32), relu (+ row norms for next kNN)
    knn_part_kernel<64, 8><<<knn_grid, 128>>>(px0, psq, ppd, ppi);
    edge_kernel<64, 32, 32, false, true><<<edge_grid, 64>>>(
        px0, ppd, ppi, pw1p1, b1_1, pw2p1, b2_1, nullptr, px1, psq);

    // ---- layer 2: x1(32) -> out(64) = relu(conv + x0)
    knn_part_kernel<32, 16><<<knn_grid, 128>>>(px1, psq, ppd, ppi);
    edge_kernel<32, 64, 64, true, false><<<edge_grid, 64>>>(
        px1, ppd, ppi, pw1p2, b1_2, pw2p2, b2_2, px0, out, nullptr);
}

// round 14
// speedup vs baseline: 1.0314x; 1.0314x over previous
#include <cuda_runtime.h>
#include <cstdint>

typedef unsigned long long ull;

static constexpr int BATCH  = 16;
static constexpr int NPTS   = 2048;
static constexpr int TOTAL  = BATCH * NPTS;    // 32768
static constexpr int KNN    = 6;
static constexpr int NSPLIT = 4;
static constexpr int CHUNK  = NPTS / NSPLIT;   // 512

// ---------------- scratch (device globals; no cudaMalloc allowed) ----------
__device__ float g_x0[TOTAL * 64];
__device__ float g_x1[TOTAL * 32];
__device__ float g_sq[TOTAL];
__device__ int   g_knn[TOTAL * KNN];
__device__ float g_pd[TOTAL * NSPLIT * KNN];
__device__ int   g_pi[TOTAL * NSPLIT * KNN];
// packed weights (feature-pair layout), shared SM-wide via L1 instead of
// being duplicated into every block's smem
__device__ ull   g_w1p0[32 * 64];
__device__ ull   g_w2p0[32 * 64];
__device__ ull   g_w1p1[64 * 32];
__device__ ull   g_w2p1[16 * 32];
__device__ ull   g_w1p2[32 * 64];
__device__ ull   g_w2p2[32 * 64];

// ---------------- f32x2 helpers --------------------------------------------
__device__ __forceinline__ ull fma2(ull a, ull b, ull c) {
    ull d;
    asm("fma.rn.f32x2 %0, %1, %2, %3;" : "=l"(d) : "l"(a), "l"(b), "l"(c));
    return d;
}
__device__ __forceinline__ ull pack2(float x, float y) {
    ull r;
    asm("mov.b64 %0, {%1, %2};" : "=l"(r) : "f"(x), "f"(y));
    return r;
}
__device__ __forceinline__ void unpack2(ull v, float& x, float& y) {
    asm("mov.b64 {%0, %1}, %2;" : "=f"(x), "=f"(y) : "l"(v));
}

// ---------------- squared norms (input layer only) -------------------------
template <int C>
__global__ void sq_kernel(const float* __restrict__ x, float* __restrict__ sq) {
    int p = blockIdx.x * 256 + threadIdx.x;
    if (p >= TOTAL) return;
    const float4* xp = reinterpret_cast<const float4*>(x + (size_t)p * C);
    float s = 0.f;
#pragma unroll
    for (int i = 0; i < C / 4; i++) {
        float4 v = xp[i];
        s += v.x * v.x + v.y * v.y + v.z * v.z + v.w * v.w;
    }
    sq[p] = s;
}

// ---------------- weight prepack (paired rows), all 3 layers in one launch --
// w1p[q*H + c]    = {W1[2q][c],   W1[2q+1][c]}   for q in [0, CIN)
// w2p[q*COUT + c] = {W2[2q][c],   W2[2q+1][c]}   for q in [0, H/2)
__device__ void prepack_one(const float* W1, const float* W2,
                            ull* w1p, ull* w2p, int CIN, int H, int COUT,
                            int idx) {
    if (idx < CIN * H) {
        int q = idx / H, c = idx % H;
        w1p[idx] = pack2(W1[(2 * q) * H + c], W1[(2 * q + 1) * H + c]);
    }
    if (idx < (H / 2) * COUT) {
        int q = idx / COUT, c = idx % COUT;
        w2p[idx] = pack2(W2[(2 * q) * COUT + c], W2[(2 * q + 1) * COUT + c]);
    }
}
__global__ void prepack_all_kernel(const float* W1_0, const float* W2_0,
                                   const float* W1_1, const float* W2_1,
                                   const float* W1_2, const float* W2_2,
                                   ull* w1p0, ull* w2p0,
                                   ull* w1p1, ull* w2p1,
                                   ull* w1p2, ull* w2p2) {
    int idx = blockIdx.x * 256 + threadIdx.x;
    if (blockIdx.y == 0)      prepack_one(W1_0, W2_0, w1p0, w2p0, 32, 64, 64, idx);
    else if (blockIdx.y == 1) prepack_one(W1_1, W2_1, w1p1, w2p1, 64, 32, 32, idx);
    else                      prepack_one(W1_2, W2_2, w1p2, w2p2, 32, 64, 64, idx);
}

// ---------------- partial kNN over one candidate chunk ---------------------
// block: 128 queries of one batch; MT-candidate tiles staged in smem in
// feature-paired layout, monolithic MT-wide accumulator burst (max ILP).
// MT=16 for C=32, MT=8 for C=64. Rank by csq - 2*dot (query norm cancels).
template <int C, int MT>
__global__ void __launch_bounds__(128)
knn_part_kernel(const float* __restrict__ x,
                const float* __restrict__ sq,
                float* __restrict__ pd, int* __restrict__ pi) {
    constexpr int SP = MT * 2 + 4;     // float stride per feature-pair row
    static_assert(MT * C == 128 * 4, "one float4 per thread per tile");
    __shared__ __align__(16) float scs[(C / 2) * SP];
    __shared__ float ssq[MT];

    const int b     = blockIdx.y;
    const int chunk = blockIdx.z;
    const int tid   = threadIdx.x;
    const int q     = blockIdx.x * 128 + tid;
    const float* xb = x + (size_t)b * NPTS * C;
    const float* sb = sq + b * NPTS;

    // query features into packed-pair registers
    ull qf[C / 2];
#pragma unroll
    for (int ip = 0; ip < C / 4; ip++) {
        float4 v = *reinterpret_cast<const float4*>(xb + (size_t)q * C + ip * 4);
        qf[2 * ip]     = pack2(v.x, v.y);
        qf[2 * ip + 1] = pack2(v.z, v.w);
    }

    const float INF = __int_as_float(0x7f800000);
    float kd[6] = {INF, INF, INF, INF, INF, INF};
    int   ki[6] = {0, 0, 0, 0, 0, 0};

    const int m_beg = chunk * CHUNK;
    for (int m0 = m_beg; m0 < m_beg + CHUNK; m0 += MT) {
        __syncthreads();
        {
            int f  = tid * 4;
            int mm = f / C, i = f % C;
            float4 v = *reinterpret_cast<const float4*>(
                xb + (size_t)(m0 + mm) * C + i);
            *reinterpret_cast<float2*>(&scs[(i >> 1) * SP + mm * 2])       = make_float2(v.x, v.y);
            *reinterpret_cast<float2*>(&scs[((i >> 1) + 1) * SP + mm * 2]) = make_float2(v.z, v.w);
        }
        if (tid < MT) ssq[tid] = sb[m0 + tid];
        __syncthreads();

        ull acc[MT];
#pragma unroll
        for (int mm = 0; mm < MT; mm++) acc[mm] = 0ull;

#pragma unroll
        for (int ip = 0; ip < C / 2; ip++) {
            ull qv = qf[ip];
            const ulonglong2* base =
                reinterpret_cast<const ulonglong2*>(&scs[ip * SP]);
#pragma unroll
            for (int mm2 = 0; mm2 < MT / 2; mm2++) {
                ulonglong2 cc = base[mm2];
                acc[2 * mm2]     = fma2(qv, cc.x, acc[2 * mm2]);
                acc[2 * mm2 + 1] = fma2(qv, cc.y, acc[2 * mm2 + 1]);
            }
        }

#pragma unroll
        for (int mm = 0; mm < MT; mm++) {
            float lo, hi;
            unpack2(acc[mm], lo, hi);
            float d = fmaf(-2.f, lo + hi, ssq[mm]);   // csq - 2*dot
            int   m = m0 + mm;
            if (m != q && d < kd[5]) {   // strict < keeps lower index on ties
                kd[5] = d; ki[5] = m;
#pragma unroll
                for (int j = 5; j > 0; j--) {
                    if (kd[j] < kd[j - 1]) {
                        float td = kd[j]; kd[j] = kd[j - 1]; kd[j - 1] = td;
                        int   ti = ki[j]; ki[j] = ki[j - 1]; ki[j - 1] = ti;
                    }
                }
            }
        }
    }

    const int base = ((b * NPTS + q) * NSPLIT + chunk) * KNN;
#pragma unroll
    for (int k = 0; k < KNN; k++) {
        pd[base + k] = kd[k];
        pi[base + k] = b * NPTS + ki[k];
    }
}

// ---------------- merge NSPLIT partial top-6 lists --------------------------
// Entries arrive in chunk order (ascending candidate index ranges), each list
// ascending distance with ties already lower-index-first; strict-< insertion
// therefore reproduces global top_k tie-breaking for set membership.
__global__ void knn_merge_kernel(const float* __restrict__ pd,
                                 const int* __restrict__ pi,
                                 int* __restrict__ knn) {
    int p = blockIdx.x * 256 + threadIdx.x;
    if (p >= TOTAL) return;
    const float INF = __int_as_float(0x7f800000);
    float kd[6] = {INF, INF, INF, INF, INF, INF};
    int   ki[6] = {0, 0, 0, 0, 0, 0};
    const int base = p * NSPLIT * KNN;
#pragma unroll
    for (int e = 0; e < NSPLIT * KNN; e++) {
        float d = pd[base + e];
        int   i = pi[base + e];
        if (d < kd[5]) {
            kd[5] = d; ki[5] = i;
#pragma unroll
            for (int j = 5; j > 0; j--) {
                if (kd[j] < kd[j - 1]) {
                    float td = kd[j]; kd[j] = kd[j - 1]; kd[j - 1] = td;
                    int   ti = ki[j]; ki[j] = ki[j - 1]; ki[j - 1] = ti;
                }
            }
        }
    }
#pragma unroll
    for (int k = 0; k < KNN; k++) knn[p * KNN + k] = ki[k];
}

// ---------------- edge MLP + max over K + (residual) + relu ----------------
// warp per point-group (8 points, processed in pairs so each weight fetch
// feeds 2 points x 6 edges x CH fma2). Weights come from prepacked GLOBAL
// arrays via __ldg (L1-resident, shared SM-wide) instead of per-block smem.
// xi half of stage-1 computed once per point.
// WSQ: fused output-row-norm write (feeds the next layer's kNN).
template <int CIN, int H, int COUT, bool RES, bool WSQ>
__global__ void __launch_bounds__(64)
edge_kernel(const float* __restrict__ x,
            const int* __restrict__ knn,
            const ull* __restrict__ w1p, const float* __restrict__ b1,
            const ull* __restrict__ w2p, const float* __restrict__ b2,
            const float* __restrict__ res, float* __restrict__ out,
            float* __restrict__ osq) {
    constexpr int WPB = 2;            // warps per block
    constexpr int PPW = 8;            // points per warp
    constexpr int PB  = 2;            // points processed together
    constexpr int CH  = H / 32;       // h1 channels per lane
    constexpr int CO  = COUT / 32;    // out channels per lane
    constexpr int RIN = CIN / 32;     // input features per lane

    __shared__ __align__(16) ull xiu[WPB][PB][CIN / 2];
    __shared__ __align__(16) ull dgu[WPB][PB][KNN][CIN / 2];
    __shared__ __align__(16) ull hbu[WPB][PB][KNN][H / 2];

    const int tid  = threadIdx.x;
    const int w    = tid >> 5;
    const int lane = tid & 31;

    float b1v[CH], b2v[CO];
#pragma unroll
    for (int cc = 0; cc < CH; cc++) b1v[cc] = b1[lane + 32 * cc];
#pragma unroll
    for (int cc = 0; cc < CO; cc++) b2v[cc] = b2[lane + 32 * cc];

    const float NINF = __int_as_float(0xff800000);
    const int p0 = (blockIdx.x * WPB + w) * PPW;

    for (int pt = 0; pt < PPW; pt += PB) {
        // xi + neighbor diffs into per-warp smem for both points
        float xr[PB][RIN];
#pragma unroll
        for (int pp = 0; pp < PB; pp++) {
            const int P = p0 + pt + pp;
            float* xif = reinterpret_cast<float*>(xiu[w][pp]);
#pragma unroll
            for (int r = 0; r < RIN; r++) {
                xr[pp][r] = x[(size_t)P * CIN + lane + 32 * r];
                xif[lane + 32 * r] = xr[pp][r];
            }
#pragma unroll
            for (int k = 0; k < KNN; k++) {
                int j = knn[P * KNN + k];
                float* dgf = reinterpret_cast<float*>(dgu[w][pp][k]);
#pragma unroll
                for (int r = 0; r < RIN; r++)
                    dgf[lane + 32 * r] =
                        x[(size_t)j * CIN + lane + 32 * r] - xr[pp][r];
            }
        }
        __syncwarp();

        // stage 1 base: xi @ W1[:CIN] (edge-invariant, shared weight loads)
        ull ab[PB][CH];
#pragma unroll
        for (int pp = 0; pp < PB; pp++)
#pragma unroll
            for (int cc = 0; cc < CH; cc++) ab[pp][cc] = 0ull;
#pragma unroll
        for (int ip = 0; ip < CIN / 2; ip++) {
            ull wv[CH];
#pragma unroll
            for (int cc = 0; cc < CH; cc++)
                wv[cc] = __ldg(&w1p[ip * H + lane + 32 * cc]);
#pragma unroll
            for (int pp = 0; pp < PB; pp++) {
                ull xv = xiu[w][pp][ip];
#pragma unroll
                for (int cc = 0; cc < CH; cc++)
                    ab[pp][cc] = fma2(xv, wv[cc], ab[pp][cc]);
            }
        }

        // stage 1 per edge: + (xj-xi) @ W1[CIN:]
        ull a2[PB][KNN][CH];
#pragma unroll
        for (int pp = 0; pp < PB; pp++)
#pragma unroll
            for (int k = 0; k < KNN; k++)
#pragma unroll
                for (int cc = 0; cc < CH; cc++) a2[pp][k][cc] = ab[pp][cc];
#pragma unroll
        for (int ip = 0; ip < CIN / 2; ip++) {
            ull wv[CH];
#pragma unroll
            for (int cc = 0; cc < CH; cc++)
                wv[cc] = __ldg(&w1p[(CIN / 2 + ip) * H + lane + 32 * cc]);
#pragma unroll
            for (int pp = 0; pp < PB; pp++)
#pragma unroll
                for (int k = 0; k < KNN; k++) {
                    ull dv = dgu[w][pp][k][ip];
#pragma unroll
                    for (int cc = 0; cc < CH; cc++)
                        a2[pp][k][cc] = fma2(dv, wv[cc], a2[pp][k][cc]);
                }
        }
#pragma unroll
        for (int pp = 0; pp < PB; pp++)
#pragma unroll
            for (int k = 0; k < KNN; k++) {
                float* hbf = reinterpret_cast<float*>(hbu[w][pp][k]);
#pragma unroll
                for (int cc = 0; cc < CH; cc++) {
                    float lo, hi;
                    unpack2(a2[pp][k][cc], lo, hi);
                    hbf[lane + 32 * cc] = fmaxf(b1v[cc] + lo + hi, 0.f);
                }
            }
        __syncwarp();

        // stage 2: o = h1 @ W2 + b2, max over edges
        ull o2[PB][KNN][CO];
#pragma unroll
        for (int pp = 0; pp < PB; pp++)
#pragma unroll
            for (int k = 0; k < KNN; k++)
#pragma unroll
                for (int cc = 0; cc < CO; cc++) o2[pp][k][cc] = 0ull;
#pragma unroll
        for (int hp = 0; hp < H / 2; hp++) {
            ull wv[CO];
#pragma unroll
            for (int cc = 0; cc < CO; cc++)
                wv[cc] = __ldg(&w2p[hp * COUT + lane + 32 * cc]);
#pragma unroll
            for (int pp = 0; pp < PB; pp++)
#pragma unroll
                for (int k = 0; k < KNN; k++) {
                    ull hv = hbu[w][pp][k][hp];
#pragma unroll
                    for (int cc = 0; cc < CO; cc++)
                        o2[pp][k][cc] = fma2(hv, wv[cc], o2[pp][k][cc]);
                }
        }
#pragma unroll
        for (int pp = 0; pp < PB; pp++) {
            const int P = p0 + pt + pp;
            float best[CO];
#pragma unroll
            for (int cc = 0; cc < CO; cc++) best[cc] = NINF;
#pragma unroll
            for (int k = 0; k < KNN; k++)
#pragma unroll
                for (int cc = 0; cc < CO; cc++) {
                    float lo, hi;
                    unpack2(o2[pp][k][cc], lo, hi);
                    best[cc] = fmaxf(best[cc], b2v[cc] + lo + hi);
                }
            float sq_acc = 0.f;
#pragma unroll
            for (int cc = 0; cc < CO; cc++) {
                int c = lane + 32 * cc;
                float v = best[cc];
                if (RES) v += res[(size_t)P * COUT + c];
                v = fmaxf(v, 0.f);
                out[(size_t)P * COUT + c] = v;
                if (WSQ) sq_acc = fmaf(v, v, sq_acc);
            }
            if (WSQ) {
                // warp-wide sum of per-lane channel squares
#pragma unroll
                for (int off = 16; off > 0; off >>= 1)
                    sq_acc += __shfl_xor_sync(0xffffffffu, sq_acc, off);
                if (lane == 0) osq[P] = sq_acc;
            }
        }
        __syncwarp();
    }
}

// ---------------- launch ----------------------------------------------------
extern "C" void kernel_launch(void* const* d_in, const int* in_sizes, int n_in,
                              void* d_out, int out_size) {
    const float* x    = (const float*)d_in[0];
    const float* W1_0 = (const float*)d_in[2];
    const float* b1_0 = (const float*)d_in[3];
    const float* W2_0 = (const float*)d_in[4];
    const float* b2_0 = (const float*)d_in[5];
    const float* W1_1 = (const float*)d_in[6];
    const float* b1_1 = (const float*)d_in[7];
    const float* W2_1 = (const float*)d_in[8];
    const float* b2_1 = (const float*)d_in[9];
    const float* W1_2 = (const float*)d_in[10];
    const float* b1_2 = (const float*)d_in[11];
    const float* W2_2 = (const float*)d_in[12];
    const float* b2_2 = (const float*)d_in[13];
    float* out = (float*)d_out;

    float *px0, *px1, *psq, *ppd;
    int *pknn, *ppi;
    ull *pw1p0, *pw2p0, *pw1p1, *pw2p1, *pw1p2, *pw2p2;
    cudaGetSymbolAddress((void**)&px0, g_x0);
    cudaGetSymbolAddress((void**)&px1, g_x1);
    cudaGetSymbolAddress((void**)&psq, g_sq);
    cudaGetSymbolAddress((void**)&pknn, g_knn);
    cudaGetSymbolAddress((void**)&ppd, g_pd);
    cudaGetSymbolAddress((void**)&ppi, g_pi);
    cudaGetSymbolAddress((void**)&pw1p0, g_w1p0);
    cudaGetSymbolAddress((void**)&pw2p0, g_w2p0);
    cudaGetSymbolAddress((void**)&pw1p1, g_w1p1);
    cudaGetSymbolAddress((void**)&pw2p1, g_w2p1);
    cudaGetSymbolAddress((void**)&pw1p2, g_w1p2);
    cudaGetSymbolAddress((void**)&pw2p2, g_w2p2);

    dim3 knn_grid(NPTS / 128, BATCH, NSPLIT);
    const int edge_grid = TOTAL / (2 * 8);   // WPB*PPW points per block

    // weight prepack for all layers (one launch) + input row norms
    prepack_all_kernel<<<dim3(8, 3), 256>>>(W1_0, W2_0, W1_1, W2_1, W1_2, W2_2,
                                            pw1p0, pw2p0, pw1p1, pw2p1,
                                            pw1p2, pw2p2);
    sq_kernel<32><<<TOTAL / 256, 256>>>(x, psq);

    // ---- layer 0: x(32) -> x0(64), relu (+ row norms for next kNN)
    knn_part_kernel<32, 16><<<knn_grid, 128>>>(x, psq, ppd, ppi);
    knn_merge_kernel<<<TOTAL / 256, 256>>>(ppd, ppi, pknn);
    edge_kernel<32, 64, 64, false, true><<<edge_grid, 64>>>(
        x, pknn, pw1p0, b1_0, pw2p0, b2_0, nullptr, px0, psq);

    // ---- layer 1: x0(64) -> x1(32), relu (+ row norms for next kNN)
    knn_part_kernel<64, 8><<<knn_grid, 128>>>(px0, psq, ppd, ppi);
    knn_merge_kernel<<<TOTAL / 256, 256>>>(ppd, ppi, pknn);
    edge_kernel<64, 32, 32, false, true><<<edge_grid, 64>>>(
        px0, pknn, pw1p1, b1_1, pw2p1, b2_1, nullptr, px1, psq);

    // ---- layer 2: x1(32) -> out(64) = relu(conv + x0)
    knn_part_kernel<32, 16><<<knn_grid, 128>>>(px1, psq, ppd, ppi);
    knn_merge_kernel<<<TOTAL / 256, 256>>>(ppd, ppi, pknn);
    edge_kernel<32, 64, 64, true, false><<<edge_grid, 64>>>(
        px1, pknn, pw1p2, b1_2, pw2p2, b2_2, px0, out, nullptr);
}

// round 15
// speedup vs baseline: 1.0394x; 1.0077x over previous
#include <cuda_runtime.h>
#include <cstdint>

typedef unsigned long long ull;

static constexpr int BATCH  = 16;
static constexpr int NPTS   = 2048;
static constexpr int TOTAL  = BATCH * NPTS;    // 32768
static constexpr int KNN    = 6;
static constexpr int NSPLIT = 4;
static constexpr int CHUNK  = NPTS / NSPLIT;   // 512

// ---------------- scratch (device globals; no cudaMalloc allowed) ----------
__device__ float g_x0[TOTAL * 64];
__device__ float g_x1[TOTAL * 32];
__device__ float g_sq[TOTAL];
__device__ int   g_knn[TOTAL * KNN];
__device__ __align__(16) ull g_pq[TOTAL * NSPLIT * KNN];   // packed (dist,idx)
// packed weights (feature-pair layout), shared SM-wide via L1 instead of
// being duplicated into every block's smem
__device__ ull   g_w1p0[32 * 64];
__device__ ull   g_w2p0[32 * 64];
__device__ ull   g_w1p1[64 * 32];
__device__ ull   g_w2p1[16 * 32];
__device__ ull   g_w1p2[32 * 64];
__device__ ull   g_w2p2[32 * 64];

// ---------------- f32x2 helpers --------------------------------------------
__device__ __forceinline__ ull fma2(ull a, ull b, ull c) {
    ull d;
    asm("fma.rn.f32x2 %0, %1, %2, %3;" : "=l"(d) : "l"(a), "l"(b), "l"(c));
    return d;
}
__device__ __forceinline__ ull pack2(float x, float y) {
    ull r;
    asm("mov.b64 %0, {%1, %2};" : "=l"(r) : "f"(x), "f"(y));
    return r;
}
__device__ __forceinline__ void unpack2(ull v, float& x, float& y) {
    asm("mov.b64 {%0, %1}, %2;" : "=f"(x), "=f"(y) : "l"(v));
}
// pack (distance float bits, index) into one 64-bit word; ORDER-NEUTRAL
// container only — comparisons always unpack and compare the float.
__device__ __forceinline__ ull pack_di(float d, int i) {
    return ((ull)__float_as_uint(d) << 32) | (unsigned)i;
}
__device__ __forceinline__ void unpack_di(ull v, float& d, int& i) {
    d = __uint_as_float((unsigned)(v >> 32));
    i = (int)(v & 0xffffffffu);
}

// ---------------- squared norms (input layer only) -------------------------
template <int C>
__global__ void sq_kernel(const float* __restrict__ x, float* __restrict__ sq) {
    int p = blockIdx.x * 256 + threadIdx.x;
    if (p >= TOTAL) return;
    const float4* xp = reinterpret_cast<const float4*>(x + (size_t)p * C);
    float s = 0.f;
#pragma unroll
    for (int i = 0; i < C / 4; i++) {
        float4 v = xp[i];
        s += v.x * v.x + v.y * v.y + v.z * v.z + v.w * v.w;
    }
    sq[p] = s;
}

// ---------------- weight prepack (paired rows), all 3 layers in one launch --
__device__ void prepack_one(const float* W1, const float* W2,
                            ull* w1p, ull* w2p, int CIN, int H, int COUT,
                            int idx) {
    if (idx < CIN * H) {
        int q = idx / H, c = idx % H;
        w1p[idx] = pack2(W1[(2 * q) * H + c], W1[(2 * q + 1) * H + c]);
    }
    if (idx < (H / 2) * COUT) {
        int q = idx / COUT, c = idx % COUT;
        w2p[idx] = pack2(W2[(2 * q) * COUT + c], W2[(2 * q + 1) * COUT + c]);
    }
}
__global__ void prepack_all_kernel(const float* W1_0, const float* W2_0,
                                   const float* W1_1, const float* W2_1,
                                   const float* W1_2, const float* W2_2,
                                   ull* w1p0, ull* w2p0,
                                   ull* w1p1, ull* w2p1,
                                   ull* w1p2, ull* w2p2) {
    int idx = blockIdx.x * 256 + threadIdx.x;
    if (blockIdx.y == 0)      prepack_one(W1_0, W2_0, w1p0, w2p0, 32, 64, 64, idx);
    else if (blockIdx.y == 1) prepack_one(W1_1, W2_1, w1p1, w2p1, 64, 32, 32, idx);
    else                      prepack_one(W1_2, W2_2, w1p2, w2p2, 32, 64, 64, idx);
}

// ---------------- partial kNN over one candidate chunk ---------------------
// block: 128 queries of one batch; MT-candidate tiles staged in smem in
// feature-paired layout, monolithic MT-wide accumulator burst (max ILP).
// MT=16 for C=32, MT=8 for C=64. Rank by csq - 2*dot (query norm cancels).
// Epilogue writes the 6 (dist,idx) pairs packed -> 3 STG.128.
template <int C, int MT>
__global__ void __launch_bounds__(128)
knn_part_kernel(const float* __restrict__ x,
                const float* __restrict__ sq,
                ull* __restrict__ pq) {
    constexpr int SP = MT * 2 + 4;     // float stride per feature-pair row
    static_assert(MT * C == 128 * 4, "one float4 per thread per tile");
    __shared__ __align__(16) float scs[(C / 2) * SP];
    __shared__ float ssq[MT];

    const int b     = blockIdx.y;
    const int chunk = blockIdx.z;
    const int tid   = threadIdx.x;
    const int q     = blockIdx.x * 128 + tid;
    const float* xb = x + (size_t)b * NPTS * C;
    const float* sb = sq + b * NPTS;

    // query features into packed-pair registers
    ull qf[C / 2];
#pragma unroll
    for (int ip = 0; ip < C / 4; ip++) {
        float4 v = *reinterpret_cast<const float4*>(xb + (size_t)q * C + ip * 4);
        qf[2 * ip]     = pack2(v.x, v.y);
        qf[2 * ip + 1] = pack2(v.z, v.w);
    }

    const float INF = __int_as_float(0x7f800000);
    float kd[6] = {INF, INF, INF, INF, INF, INF};
    int   ki[6] = {0, 0, 0, 0, 0, 0};

    const int m_beg = chunk * CHUNK;
    for (int m0 = m_beg; m0 < m_beg + CHUNK; m0 += MT) {
        __syncthreads();
        {
            int f  = tid * 4;
            int mm = f / C, i = f % C;
            float4 v = *reinterpret_cast<const float4*>(
                xb + (size_t)(m0 + mm) * C + i);
            *reinterpret_cast<float2*>(&scs[(i >> 1) * SP + mm * 2])       = make_float2(v.x, v.y);
            *reinterpret_cast<float2*>(&scs[((i >> 1) + 1) * SP + mm * 2]) = make_float2(v.z, v.w);
        }
        if (tid < MT) ssq[tid] = sb[m0 + tid];
        __syncthreads();

        ull acc[MT];
#pragma unroll
        for (int mm = 0; mm < MT; mm++) acc[mm] = 0ull;

#pragma unroll
        for (int ip = 0; ip < C / 2; ip++) {
            ull qv = qf[ip];
            const ulonglong2* base =
                reinterpret_cast<const ulonglong2*>(&scs[ip * SP]);
#pragma unroll
            for (int mm2 = 0; mm2 < MT / 2; mm2++) {
                ulonglong2 cc = base[mm2];
                acc[2 * mm2]     = fma2(qv, cc.x, acc[2 * mm2]);
                acc[2 * mm2 + 1] = fma2(qv, cc.y, acc[2 * mm2 + 1]);
            }
        }

#pragma unroll
        for (int mm = 0; mm < MT; mm++) {
            float lo, hi;
            unpack2(acc[mm], lo, hi);
            float d = fmaf(-2.f, lo + hi, ssq[mm]);   // csq - 2*dot
            int   m = m0 + mm;
            if (m != q && d < kd[5]) {   // strict < keeps lower index on ties
                kd[5] = d; ki[5] = m;
#pragma unroll
                for (int j = 5; j > 0; j--) {
                    if (kd[j] < kd[j - 1]) {
                        float td = kd[j]; kd[j] = kd[j - 1]; kd[j - 1] = td;
                        int   ti = ki[j]; ki[j] = ki[j - 1]; ki[j - 1] = ti;
                    }
                }
            }
        }
    }

    const int base = ((b * NPTS + q) * NSPLIT + chunk) * KNN;
    ulonglong2* outp = reinterpret_cast<ulonglong2*>(pq + base);
#pragma unroll
    for (int k = 0; k < KNN / 2; k++) {
        ulonglong2 v;
        v.x = pack_di(kd[2 * k],     b * NPTS + ki[2 * k]);
        v.y = pack_di(kd[2 * k + 1], b * NPTS + ki[2 * k + 1]);
        outp[k] = v;
    }
}

// ---------------- merge NSPLIT partial top-6 lists --------------------------
// Packed entries are read with vector loads, then unpacked; the insertion
// compares the FLOAT distance with strict < in chunk order — selection
// semantics identical to the original scalar merge.
__global__ void __launch_bounds__(128)
knn_merge_kernel(const ull* __restrict__ pq, int* __restrict__ knn) {
    int p = blockIdx.x * 128 + threadIdx.x;
    if (p >= TOTAL) return;
    const float INF = __int_as_float(0x7f800000);
    float kd[6] = {INF, INF, INF, INF, INF, INF};
    int   ki[6] = {0, 0, 0, 0, 0, 0};
    const ulonglong2* inp =
        reinterpret_cast<const ulonglong2*>(pq + (size_t)p * NSPLIT * KNN);
#pragma unroll
    for (int e2 = 0; e2 < NSPLIT * KNN / 2; e2++) {
        ulonglong2 v = inp[e2];
#pragma unroll
        for (int half = 0; half < 2; half++) {
            float d; int i;
            unpack_di(half ? v.y : v.x, d, i);
            if (d < kd[5]) {
                kd[5] = d; ki[5] = i;
#pragma unroll
                for (int j = 5; j > 0; j--) {
                    if (kd[j] < kd[j - 1]) {
                        float td = kd[j]; kd[j] = kd[j - 1]; kd[j - 1] = td;
                        int   ti = ki[j]; ki[j] = ki[j - 1]; ki[j - 1] = ti;
                    }
                }
            }
        }
    }
#pragma unroll
    for (int k = 0; k < KNN; k++) knn[p * KNN + k] = ki[k];
}

// ---------------- edge MLP + max over K + (residual) + relu ----------------
// warp per point-group (8 points, processed in pairs so each weight fetch
// feeds 2 points x 6 edges x CH fma2). Weights come from prepacked GLOBAL
// arrays via __ldg (L1-resident, shared SM-wide) instead of per-block smem.
// xi half of stage-1 computed once per point.
// WSQ: fused output-row-norm write (feeds the next layer's kNN).
template <int CIN, int H, int COUT, bool RES, bool WSQ>
__global__ void __launch_bounds__(64)
edge_kernel(const float* __restrict__ x,
            const int* __restrict__ knn,
            const ull* __restrict__ w1p, const float* __restrict__ b1,
            const ull* __restrict__ w2p, const float* __restrict__ b2,
            const float* __restrict__ res, float* __restrict__ out,
            float* __restrict__ osq) {
    constexpr int WPB = 2;            // warps per block
    constexpr int PPW = 8;            // points per warp
    constexpr int PB  = 2;            // points processed together
    constexpr int CH  = H / 32;       // h1 channels per lane
    constexpr int CO  = COUT / 32;    // out channels per lane
    constexpr int RIN = CIN / 32;     // input features per lane

    __shared__ __align__(16) ull xiu[WPB][PB][CIN / 2];
    __shared__ __align__(16) ull dgu[WPB][PB][KNN][CIN / 2];
    __shared__ __align__(16) ull hbu[WPB][PB][KNN][H / 2];

    const int tid  = threadIdx.x;
    const int w    = tid >> 5;
    const int lane = tid & 31;

    float b1v[CH], b2v[CO];
#pragma unroll
    for (int cc = 0; cc < CH; cc++) b1v[cc] = b1[lane + 32 * cc];
#pragma unroll
    for (int cc = 0; cc < CO; cc++) b2v[cc] = b2[lane + 32 * cc];

    const float NINF = __int_as_float(0xff800000);
    const int p0 = (blockIdx.x * WPB + w) * PPW;

    for (int pt = 0; pt < PPW; pt += PB) {
        // xi + neighbor diffs into per-warp smem for both points
        float xr[PB][RIN];
#pragma unroll
        for (int pp = 0; pp < PB; pp++) {
            const int P = p0 + pt + pp;
            float* xif = reinterpret_cast<float*>(xiu[w][pp]);
#pragma unroll
            for (int r = 0; r < RIN; r++) {
                xr[pp][r] = x[(size_t)P * CIN + lane + 32 * r];
                xif[lane + 32 * r] = xr[pp][r];
            }
#pragma unroll
            for (int k = 0; k < KNN; k++) {
                int j = knn[P * KNN + k];
                float* dgf = reinterpret_cast<float*>(dgu[w][pp][k]);
#pragma unroll
                for (int r = 0; r < RIN; r++)
                    dgf[lane + 32 * r] =
                        x[(size_t)j * CIN + lane + 32 * r] - xr[pp][r];
            }
        }
        __syncwarp();

        // stage 1 base: xi @ W1[:CIN] (edge-invariant, shared weight loads)
        ull ab[PB][CH];
#pragma unroll
        for (int pp = 0; pp < PB; pp++)
#pragma unroll
            for (int cc = 0; cc < CH; cc++) ab[pp][cc] = 0ull;
#pragma unroll
        for (int ip = 0; ip < CIN / 2; ip++) {
            ull wv[CH];
#pragma unroll
            for (int cc = 0; cc < CH; cc++)
                wv[cc] = __ldg(&w1p[ip * H + lane + 32 * cc]);
#pragma unroll
            for (int pp = 0; pp < PB; pp++) {
                ull xv = xiu[w][pp][ip];
#pragma unroll
                for (int cc = 0; cc < CH; cc++)
                    ab[pp][cc] = fma2(xv, wv[cc], ab[pp][cc]);
            }
        }

        // stage 1 per edge: + (xj-xi) @ W1[CIN:]
        ull a2[PB][KNN][CH];
#pragma unroll
        for (int pp = 0; pp < PB; pp++)
#pragma unroll
            for (int k = 0; k < KNN; k++)
#pragma unroll
                for (int cc = 0; cc < CH; cc++) a2[pp][k][cc] = ab[pp][cc];
#pragma unroll
        for (int ip = 0; ip < CIN / 2; ip++) {
            ull wv[CH];
#pragma unroll
            for (int cc = 0; cc < CH; cc++)
                wv[cc] = __ldg(&w1p[(CIN / 2 + ip) * H + lane + 32 * cc]);
#pragma unroll
            for (int pp = 0; pp < PB; pp++)
#pragma unroll
                for (int k = 0; k < KNN; k++) {
                    ull dv = dgu[w][pp][k][ip];
#pragma unroll
                    for (int cc = 0; cc < CH; cc++)
                        a2[pp][k][cc] = fma2(dv, wv[cc], a2[pp][k][cc]);
                }
        }
#pragma unroll
        for (int pp = 0; pp < PB; pp++)
#pragma unroll
            for (int k = 0; k < KNN; k++) {
                float* hbf = reinterpret_cast<float*>(hbu[w][pp][k]);
#pragma unroll
                for (int cc = 0; cc < CH; cc++) {
                    float lo, hi;
                    unpack2(a2[pp][k][cc], lo, hi);
                    hbf[lane + 32 * cc] = fmaxf(b1v[cc] + lo + hi, 0.f);
                }
            }
        __syncwarp();

        // stage 2: o = h1 @ W2 + b2, max over edges
        ull o2[PB][KNN][CO];
#pragma unroll
        for (int pp = 0; pp < PB; pp++)
#pragma unroll
            for (int k = 0; k < KNN; k++)
#pragma unroll
                for (int cc = 0; cc < CO; cc++) o2[pp][k][cc] = 0ull;
#pragma unroll
        for (int hp = 0; hp < H / 2; hp++) {
            ull wv[CO];
#pragma unroll
            for (int cc = 0; cc < CO; cc++)
                wv[cc] = __ldg(&w2p[hp * COUT + lane + 32 * cc]);
#pragma unroll
            for (int pp = 0; pp < PB; pp++)
#pragma unroll
                for (int k = 0; k < KNN; k++) {
                    ull hv = hbu[w][pp][k][hp];
#pragma unroll
                    for (int cc = 0; cc < CO; cc++)
                        o2[pp][k][cc] = fma2(hv, wv[cc], o2[pp][k][cc]);
                }
        }
#pragma unroll
        for (int pp = 0; pp < PB; pp++) {
            const int P = p0 + pt + pp;
            float best[CO];
#pragma unroll
            for (int cc = 0; cc < CO; cc++) best[cc] = NINF;
#pragma unroll
            for (int k = 0; k < KNN; k++)
#pragma unroll
                for (int cc = 0; cc < CO; cc++) {
                    float lo, hi;
                    unpack2(o2[pp][k][cc], lo, hi);
                    best[cc] = fmaxf(best[cc], b2v[cc] + lo + hi);
                }
            float sq_acc = 0.f;
#pragma unroll
            for (int cc = 0; cc < CO; cc++) {
                int c = lane + 32 * cc;
                float v = best[cc];
                if (RES) v += res[(size_t)P * COUT + c];
                v = fmaxf(v, 0.f);
                out[(size_t)P * COUT + c] = v;
                if (WSQ) sq_acc = fmaf(v, v, sq_acc);
            }
            if (WSQ) {
                // warp-wide sum of per-lane channel squares
#pragma unroll
                for (int off = 16; off > 0; off >>= 1)
                    sq_acc += __shfl_xor_sync(0xffffffffu, sq_acc, off);
                if (lane == 0) osq[P] = sq_acc;
            }
        }
        __syncwarp();
    }
}

// ---------------- launch ----------------------------------------------------
extern "C" void kernel_launch(void* const* d_in, const int* in_sizes, int n_in,
                              void* d_out, int out_size) {
    const float* x    = (const float*)d_in[0];
    const float* W1_0 = (const float*)d_in[2];
    const float* b1_0 = (const float*)d_in[3];
    const float* W2_0 = (const float*)d_in[4];
    const float* b2_0 = (const float*)d_in[5];
    const float* W1_1 = (const float*)d_in[6];
    const float* b1_1 = (const float*)d_in[7];
    const float* W2_1 = (const float*)d_in[8];
    const float* b2_1 = (const float*)d_in[9];
    const float* W1_2 = (const float*)d_in[10];
    const float* b1_2 = (const float*)d_in[11];
    const float* W2_2 = (const float*)d_in[12];
    const float* b2_2 = (const float*)d_in[13];
    float* out = (float*)d_out;

    float *px0, *px1, *psq;
    int *pknn;
    ull *ppq;
    ull *pw1p0, *pw2p0, *pw1p1, *pw2p1, *pw1p2, *pw2p2;
    cudaGetSymbolAddress((void**)&px0, g_x0);
    cudaGetSymbolAddress((void**)&px1, g_x1);
    cudaGetSymbolAddress((void**)&psq, g_sq);
    cudaGetSymbolAddress((void**)&pknn, g_knn);
    cudaGetSymbolAddress((void**)&ppq, g_pq);
    cudaGetSymbolAddress((void**)&pw1p0, g_w1p0);
    cudaGetSymbolAddress((void**)&pw2p0, g_w2p0);
    cudaGetSymbolAddress((void**)&pw1p1, g_w1p1);
    cudaGetSymbolAddress((void**)&pw2p1, g_w2p1);
    cudaGetSymbolAddress((void**)&pw1p2, g_w1p2);
    cudaGetSymbolAddress((void**)&pw2p2, g_w2p2);

    dim3 knn_grid(NPTS / 128, BATCH, NSPLIT);
    const int edge_grid  = TOTAL / (2 * 8);   // WPB*PPW points per block
    const int merge_grid = TOTAL / 128;

    // weight prepack for all layers (one launch) + input row norms
    prepack_all_kernel<<<dim3(8, 3), 256>>>(W1_0, W2_0, W1_1, W2_1, W1_2, W2_2,
                                            pw1p0, pw2p0, pw1p1, pw2p1,
                                            pw1p2, pw2p2);
    sq_kernel<32><<<TOTAL / 256, 256>>>(x, psq);

    // ---- layer 0: x(32) -> x0(64), relu (+ row norms for next kNN)
    knn_part_kernel<32, 16><<<knn_grid, 128>>>(x, psq, ppq);
    knn_merge_kernel<<<merge_grid, 128>>>(ppq, pknn);
    edge_kernel<32, 64, 64, false, true><<<edge_grid, 64>>>(
        x, pknn, pw1p0, b1_0, pw2p0, b2_0, nullptr, px0, psq);

    // ---- layer 1: x0(64) -> x1(32), relu (+ row norms for next kNN)
    knn_part_kernel<64, 8><<<knn_grid, 128>>>(px0, psq, ppq);
    knn_merge_kernel<<<merge_grid, 128>>>(ppq, pknn);
    edge_kernel<64, 32, 32, false, true><<<edge_grid, 64>>>(
        px0, pknn, pw1p1, b1_1, pw2p1, b2_1, nullptr, px1, psq);

    // ---- layer 2: x1(32) -> out(64) = relu(conv + x0)
    knn_part_kernel<32, 16><<<knn_grid, 128>>>(px1, psq, ppq);
    knn_merge_kernel<<<merge_grid, 128>>>(ppq, pknn);
    edge_kernel<32, 64, 64, true, false><<<edge_grid, 64>>>(
        px1, pknn, pw1p2, b1_2, pw2p2, b2_2, px0, out, nullptr);
}